// round 13
// baseline (speedup 1.0000x reference)
#include <cuda_runtime.h>
#include <cuda_bf16.h>
#include <cstdint>

// ============================================================================
// B=8, L=2048, D=1024, FF_MULT=2  ->  M = 16384 tokens
// Flips cancel; fwd+bwd fused into one wide MLP. 4 bf16 mma.sync GEMMs
// (toolchain compiles via compute_100: no tcgen05/'a' features available).
// GEMM: BM=128, BN=128, BK=32, 3-stage single-sync ring, warp tile 64x32,
// A-fragments for both ks batched upfront (latency overlap probe).
// LN: warp-per-row, no block barriers (was block-per-row, 2 syncs).
// Closed: BK=64 (r4/5,r9), BN=64/3CTA (r11), warp-shape swaps (r12 neutral).
// ============================================================================

#define MTOK   16384
#define DDIM   1024
#define DFF    2048

// --------------------------- scratch (static device globals) ----------------
__device__ __nv_bfloat16 g_norm [ (size_t)MTOK * DDIM ];
__device__ __nv_bfloat16 g_hcat [ (size_t)MTOK * DFF  ];
__device__ float          g_x2  [ (size_t)MTOK * DDIM ];
__device__ __nv_bfloat16 g_wcat1[ (size_t)DDIM * DFF ];    // [1024,2048]
__device__ __nv_bfloat16 g_wcat2[ (size_t)DFF * DDIM ];    // [2048,1024]
__device__ __nv_bfloat16 g_ffw1 [ (size_t)DDIM * DFF ];
__device__ __nv_bfloat16 g_ffw2 [ (size_t)DFF * DDIM ];
__device__ float          g_emb [ 2 * 8 * 3072 ];
__device__ float          g_emb_part[8 * 6144 * 8];        // [kz][cg][b]
__device__ float          g_bcat1[DFF];
__device__ float          g_bcat2[DDIM];

// --------------------------- small helpers ----------------------------------
__device__ __forceinline__ float gelu_erf_f(float x)  { return 0.5f * x * (1.0f + erff(x * 0.70710678118654752f)); }
__device__ __forceinline__ float gelu_tanh_f(float x) {
    float x3 = x * x * x;
    return 0.5f * x * (1.0f + tanhf(0.7978845608028654f * (x + 0.044715f * x3)));
}

__device__ __forceinline__ void cp_async16(void* smem_ptr, const void* gptr) {
    uint32_t s = (uint32_t)__cvta_generic_to_shared(smem_ptr);
    asm volatile("cp.async.cg.shared.global [%0], [%1], 16;\n" :: "r"(s), "l"(gptr));
}
#define CP_COMMIT() asm volatile("cp.async.commit_group;\n" ::)
#define CP_WAIT(N_) asm volatile("cp.async.wait_group %0;\n" :: "n"(N_))

__device__ __forceinline__ void ldsm_x4(uint32_t* r, const void* p) {
    uint32_t a = (uint32_t)__cvta_generic_to_shared(p);
    asm volatile("ldmatrix.sync.aligned.m8n8.x4.shared.b16 {%0,%1,%2,%3}, [%4];"
                 : "=r"(r[0]), "=r"(r[1]), "=r"(r[2]), "=r"(r[3]) : "r"(a));
}
__device__ __forceinline__ void ldsm_x4_t(uint32_t* r, const void* p) {
    uint32_t a = (uint32_t)__cvta_generic_to_shared(p);
    asm volatile("ldmatrix.sync.aligned.m8n8.x4.trans.shared.b16 {%0,%1,%2,%3}, [%4];"
                 : "=r"(r[0]), "=r"(r[1]), "=r"(r[2]), "=r"(r[3]) : "r"(a));
}
__device__ __forceinline__ void mma16816(float* c, const uint32_t* a, uint32_t b0, uint32_t b1) {
    asm volatile("mma.sync.aligned.m16n8k16.row.col.f32.bf16.bf16.f32 "
                 "{%0,%1,%2,%3}, {%4,%5,%6,%7}, {%8,%9}, {%0,%1,%2,%3};"
                 : "+f"(c[0]), "+f"(c[1]), "+f"(c[2]), "+f"(c[3])
                 : "r"(a[0]), "r"(a[1]), "r"(a[2]), "r"(a[3]), "r"(b0), "r"(b1));
}

// --------------------------- adaLN embedding: split-K two-phase --------------
__global__ __launch_bounds__(256) void emb_part_kernel(
    const float* __restrict__ t,
    const float* __restrict__ ada_w, const float* __restrict__ ffada_w)
{
    __shared__ float st[8][128];
    const int tid = threadIdx.x;
    const int kz  = blockIdx.y;
    const int k0  = kz * 128;
    for (int i = tid; i < 8 * 128; i += 256) {
        int b = i >> 7, kk = i & 127;
        float tv = t[b * 1024 + k0 + kk];
        st[b][kk] = tv / (1.0f + expf(-tv));
    }
    __syncthreads();

    const int cg = blockIdx.x * 256 + tid;          // 0..6143
    const float* w = (cg < 3072) ? ada_w : ffada_w;
    const int col  = (cg < 3072) ? cg : cg - 3072;

    float acc[8];
#pragma unroll
    for (int b = 0; b < 8; ++b) acc[b] = 0.0f;
#pragma unroll 4
    for (int k = 0; k < 128; ++k) {
        float wv = w[(size_t)(k0 + k) * 3072 + col];
#pragma unroll
        for (int b = 0; b < 8; ++b) acc[b] += st[b][k] * wv;
    }
    float* out = g_emb_part + ((size_t)kz * 6144 + cg) * 8;
#pragma unroll
    for (int b = 0; b < 8; ++b) out[b] = acc[b];
}

__global__ __launch_bounds__(256) void emb_reduce_kernel(
    const float* __restrict__ ada_b, const float* __restrict__ ffada_b)
{
    int idx = blockIdx.x * 256 + threadIdx.x;       // 0..49151
    int cg = idx >> 3, b = idx & 7;
    float s = 0.f;
#pragma unroll
    for (int kz = 0; kz < 8; ++kz)
        s += g_emb_part[((size_t)kz * 6144 + cg) * 8 + b];
    if (cg < 3072) g_emb[b * 3072 + cg] = s + ada_b[cg];
    else           g_emb[8 * 3072 + b * 3072 + (cg - 3072)] = s + ffada_b[cg - 3072];
}

// --------------------------- weight pack / convert ---------------------------
__global__ __launch_bounds__(256) void pack_kernel(
    const float* __restrict__ ssm_w1, const float* __restrict__ bwd_w1,
    const float* __restrict__ ssm_w2, const float* __restrict__ bwd_w2,
    const float* __restrict__ ff_w1,  const float* __restrict__ ff_w2,
    const float* __restrict__ ssm_b1, const float* __restrict__ bwd_b1,
    const float* __restrict__ ssm_b2, const float* __restrict__ bwd_b2)
{
    const long W = (long)1024 * 2048;
    long i = (long)blockIdx.x * 256 + threadIdx.x;
    const long total = 4 * W + 3072;
    if (i >= total) return;

    if (i < W) {
        int k = (int)(i >> 11), j = (int)(i & 2047);
        float v = (j < 1024) ? ssm_w1[(size_t)k * 1024 + j]
                             : bwd_w1[(size_t)k * 1024 + (j - 1024)];
        g_wcat1[i] = __float2bfloat16(v);
    } else if (i < 2 * W) {
        long q = i - W;
        int k = (int)(q >> 10), j = (int)(q & 1023);
        float v = (k < 1024) ? ssm_w2[(size_t)k * 1024 + j]
                             : bwd_w2[(size_t)(k - 1024) * 1024 + j];
        g_wcat2[q] = __float2bfloat16(v);
    } else if (i < 3 * W) {
        long q = i - 2 * W;
        g_ffw1[q] = __float2bfloat16(ff_w1[q]);
    } else if (i < 4 * W) {
        long q = i - 3 * W;
        g_ffw2[q] = __float2bfloat16(ff_w2[q]);
    } else {
        long q = i - 4 * W;
        if (q < 2048) g_bcat1[q] = (q < 1024) ? ssm_b1[q] : bwd_b1[q - 1024];
        else          g_bcat2[q - 2048] = ssm_b2[q - 2048] + bwd_b2[q - 2048];
    }
}

// --------------------------- layernorm + adaLN modulation --------------------
// Warp-per-row: 8 warps/block = 8 rows/block, zero block barriers. Each
// thread: 8 float4 loads (MLP=8), butterfly-shuffle reduction (result in all
// lanes), 8 uint2 stores. Old block-per-row version was issue/overhead bound
// (31.6us at 29% DRAM, 2 syncthreads per 4KB row).
__global__ __launch_bounds__(256) void ln_mod_kernel(
    const float* __restrict__ X, const float* __restrict__ embp,
    const int* __restrict__ mask, __nv_bfloat16* __restrict__ out, int use_mask)
{
    const int warp = threadIdx.x >> 5, lane = threadIdx.x & 31;
    const int row  = blockIdx.x * 8 + warp;
    const int b    = row >> 11;

    const float4* xr = reinterpret_cast<const float4*>(X + (size_t)row * 1024);
    float4 v[8];
    float s = 0.f, s2 = 0.f;
#pragma unroll
    for (int i = 0; i < 8; ++i) {
        v[i] = xr[lane + 32 * i];
        s  += v[i].x + v[i].y + v[i].z + v[i].w;
        s2 += v[i].x * v[i].x + v[i].y * v[i].y + v[i].z * v[i].z + v[i].w * v[i].w;
    }
#pragma unroll
    for (int off = 16; off > 0; off >>= 1) {
        s  += __shfl_xor_sync(0xffffffffu, s,  off);
        s2 += __shfl_xor_sync(0xffffffffu, s2, off);
    }
    const float mu   = s * (1.0f / 1024.0f);
    const float rstd = rsqrtf(s2 * (1.0f / 1024.0f) - mu * mu + 1e-6f);

    const int mk = use_mask ? mask[row] : 1;
    const float* eb = embp + b * 3072;
#pragma unroll
    for (int i = 0; i < 8; ++i) {
        const int d0 = (lane + 32 * i) * 4;
        float vv[4] = {v[i].x, v[i].y, v[i].z, v[i].w};
        union { __nv_bfloat16 o[4]; uint2 u; } pack;
#pragma unroll
        for (int q = 0; q < 4; ++q) {
            int d = d0 + q;
            float y = mk ? ((vv[q] - mu) * rstd * (1.0f + eb[1024 + d]) + eb[d]) : 0.0f;
            pack.o[q] = __float2bfloat16(y);
        }
        *reinterpret_cast<uint2*>(out + (size_t)row * 1024 + d0) = pack.u;
    }
}

// --------------------------- bf16 GEMM with fused epilogues ------------------
// C[M,N] = A[M,K] @ B[K,N]. BM=128, BN=128, BK=32, 3-stage single-sync ring,
// warp grid 2m x 4n (tile 64x32). THIS ROUND: A-fragments for BOTH ks steps
// loaded upfront (afr[2][4][4]=32 regs), bfr per-ks (8) -> forces ldsm issue
// ahead of the MMA chains to cover scoreboard latency (tensor 53%, issue 35%,
// no pipe saturated => exposed latency). Peak regs ~120 (r4's spill had BK=64
// addressing on top; this keeps the BK=32 loader).
// MODE 0: bf16=gelu_erf(acc+bias)  MODE 2: bf16=gelu_tanh(acc+bias)
// MODE 1: f32=res+gate*(mask?acc+bias:0)  MODE 3: f32=res+gate*(acc+bias)
#define GBM 128
#define GBN 128
#define GBK 32
#define A_ROW_B   80                       // 40 bf16 = 5 x 16B (odd)
#define B_ROW_B   272                      // 136 bf16 = 17 x 16B (odd)
#define A_STAGE_B (GBM * A_ROW_B)          // 10240
#define B_STAGE_B (GBK * B_ROW_B)          // 8704
#define STAGE_B   (A_STAGE_B + B_STAGE_B)  // 18944
#define SMEM_DYN  (3 * STAGE_B)            // 56832

template <int MODE>
__global__ __launch_bounds__(256, 2) void gemm_bf16(
    const __nv_bfloat16* __restrict__ A, const __nv_bfloat16* __restrict__ Bw,
    const float* __restrict__ bias, int N, int K,
    const float* __restrict__ res, const float* __restrict__ gate_base,
    const int* __restrict__ mask,
    float* __restrict__ outf, __nv_bfloat16* __restrict__ outb)
{
    extern __shared__ __align__(16) char sm[];

    const int tid  = threadIdx.x;
    const int warp = tid >> 5, lane = tid & 31;
    const int wm = warp >> 2, wn = warp & 3;        // 2m x 4n warps, tile 64x32
    const int bm = blockIdx.y * GBM;
    const int bn = blockIdx.x * GBN;
    const int KT = K / GBK;

    float acc[4][4][4];                             // [m-frag][n8-frag][reg]
#pragma unroll
    for (int i = 0; i < 4; ++i)
#pragma unroll
        for (int j = 0; j < 4; ++j)
#pragma unroll
            for (int q = 0; q < 4; ++q) acc[i][j][q] = 0.0f;

    // loaders (r8-proven): A 64 rows/pass x 32 cols; B 16 rows/pass x 128 cols
    const int ar = tid >> 2, ac = (tid & 3) * 8;
    const int br = tid >> 4, bc = (tid & 15) * 8;

    auto a_ptr = [&](int s, int r, int c) -> char* {
        return sm + s * STAGE_B + r * A_ROW_B + c * 2;
    };
    auto b_ptr = [&](int s, int r, int c) -> char* {
        return sm + s * STAGE_B + A_STAGE_B + r * B_ROW_B + c * 2;
    };

    auto load_stage = [&](int s, int kt) {
        const int k0 = kt * GBK;
#pragma unroll
        for (int rr = 0; rr < 2; ++rr)
            cp_async16(a_ptr(s, ar + rr * 64, ac),
                       A + (size_t)(bm + ar + rr * 64) * K + k0 + ac);
#pragma unroll
        for (int rr = 0; rr < 2; ++rr)
            cp_async16(b_ptr(s, br + rr * 16, bc),
                       Bw + (size_t)(k0 + br + rr * 16) * N + bn + bc);
        CP_COMMIT();
    };

    load_stage(0, 0);
    load_stage(1, 1);

    const int arow0 = wm * 64 + (lane & 15);
    const int hi8   = ((lane >> 4) & 1) << 3;
    const int brow0 = lane & 15;

    for (int kt = 0; kt < KT; ++kt) {
        const int s = kt % 3;
        if (kt + 1 < KT) CP_WAIT(1); else CP_WAIT(0);
        __syncthreads();
        if (kt + 2 < KT) load_stage((kt + 2) % 3, kt + 2);

        // Batch ALL A-fragment ldsm (both ks) upfront: 8 back-to-back ldsm
        // whose latency overlaps the subsequent B-ldsm + MMA chains.
        uint32_t afr[2][4][4];
#pragma unroll
        for (int ks2 = 0; ks2 < 2; ++ks2)
#pragma unroll
            for (int i = 0; i < 4; ++i)
                ldsm_x4(afr[ks2][i], a_ptr(s, arow0 + i * 16, ks2 * 16 + hi8));

#pragma unroll
        for (int ks2 = 0; ks2 < 2; ++ks2) {
            uint32_t bfr[2][4];
            const int brow = ks2 * 16 + brow0;
#pragma unroll
            for (int j = 0; j < 2; ++j)
                ldsm_x4_t(bfr[j], b_ptr(s, brow, wn * 32 + j * 16 + hi8));
#pragma unroll
            for (int i = 0; i < 4; ++i)
#pragma unroll
                for (int j = 0; j < 2; ++j) {
                    mma16816(acc[i][2 * j + 0], afr[ks2][i], bfr[j][0], bfr[j][1]);
                    mma16816(acc[i][2 * j + 1], afr[ks2][i], bfr[j][2], bfr[j][3]);
                }
        }
    }

    // ------------------------------ epilogue ------------------------------
#pragma unroll
    for (int i = 0; i < 4; ++i) {
#pragma unroll
        for (int j = 0; j < 4; ++j) {
            const int mrow0 = bm + wm * 64 + i * 16 + (lane >> 2);
            const int ncol  = bn + wn * 32 + j * 8 + (lane & 3) * 2;
#pragma unroll
            for (int h = 0; h < 2; ++h) {
                const int row = mrow0 + h * 8;
                float v0 = acc[i][j][h * 2 + 0] + bias[ncol];
                float v1 = acc[i][j][h * 2 + 1] + bias[ncol + 1];
                if constexpr (MODE == 0 || MODE == 2) {
                    if constexpr (MODE == 0) { v0 = gelu_erf_f(v0);  v1 = gelu_erf_f(v1); }
                    else                     { v0 = gelu_tanh_f(v0); v1 = gelu_tanh_f(v1); }
                    __nv_bfloat162 p;
                    p.x = __float2bfloat16(v0);
                    p.y = __float2bfloat16(v1);
                    *reinterpret_cast<__nv_bfloat162*>(outb + (size_t)row * N + ncol) = p;
                } else {
                    const int b = row >> 11;
                    if constexpr (MODE == 1) {
                        if (!mask[row]) { v0 = 0.0f; v1 = 0.0f; }
                    }
                    const float g0 = gate_base[b * 3072 + ncol];
                    const float g1 = gate_base[b * 3072 + ncol + 1];
                    float2 r;
                    r.x = res[(size_t)row * N + ncol]     + g0 * v0;
                    r.y = res[(size_t)row * N + ncol + 1] + g1 * v1;
                    *reinterpret_cast<float2*>(outf + (size_t)row * N + ncol) = r;
                }
            }
        }
    }
}

// --------------------------- launch ------------------------------------------
extern "C" void kernel_launch(void* const* d_in, const int* in_sizes, int n_in,
                              void* d_out, int out_size)
{
    const float* x       = (const float*)d_in[0];
    const float* t       = (const float*)d_in[1];
    const int*   mask    = (const int*)  d_in[2];
    const float* ada_w   = (const float*)d_in[3];
    const float* ada_b   = (const float*)d_in[4];
    const float* ssm_w1  = (const float*)d_in[5];
    const float* ssm_b1  = (const float*)d_in[6];
    const float* ssm_w2  = (const float*)d_in[7];
    const float* ssm_b2  = (const float*)d_in[8];
    const float* bwd_w1  = (const float*)d_in[9];
    const float* bwd_b1  = (const float*)d_in[10];
    const float* bwd_w2  = (const float*)d_in[11];
    const float* bwd_b2  = (const float*)d_in[12];
    const float* ffada_w = (const float*)d_in[13];
    const float* ffada_b = (const float*)d_in[14];
    const float* ff_w1   = (const float*)d_in[15];
    const float* ff_b1   = (const float*)d_in[16];
    const float* ff_w2   = (const float*)d_in[17];
    const float* ff_b2   = (const float*)d_in[18];

    void *p_norm, *p_hcat, *p_x2, *p_w1, *p_w2, *p_fw1, *p_fw2, *p_emb, *p_b1, *p_b2;
    cudaGetSymbolAddress(&p_norm, g_norm);
    cudaGetSymbolAddress(&p_hcat, g_hcat);
    cudaGetSymbolAddress(&p_x2,   g_x2);
    cudaGetSymbolAddress(&p_w1,   g_wcat1);
    cudaGetSymbolAddress(&p_w2,   g_wcat2);
    cudaGetSymbolAddress(&p_fw1,  g_ffw1);
    cudaGetSymbolAddress(&p_fw2,  g_ffw2);
    cudaGetSymbolAddress(&p_emb,  g_emb);
    cudaGetSymbolAddress(&p_b1,   g_bcat1);
    cudaGetSymbolAddress(&p_b2,   g_bcat2);

    __nv_bfloat16* norm = (__nv_bfloat16*)p_norm;
    __nv_bfloat16* hcat = (__nv_bfloat16*)p_hcat;
    float*         x2   = (float*)p_x2;
    float*         emb  = (float*)p_emb;

    cudaFuncSetAttribute(gemm_bf16<0>, cudaFuncAttributeMaxDynamicSharedMemorySize, SMEM_DYN);
    cudaFuncSetAttribute(gemm_bf16<1>, cudaFuncAttributeMaxDynamicSharedMemorySize, SMEM_DYN);
    cudaFuncSetAttribute(gemm_bf16<2>, cudaFuncAttributeMaxDynamicSharedMemorySize, SMEM_DYN);
    cudaFuncSetAttribute(gemm_bf16<3>, cudaFuncAttributeMaxDynamicSharedMemorySize, SMEM_DYN);

    // 1. adaLN embeddings (split-K two-phase)
    emb_part_kernel<<<dim3(24, 8), 256>>>(t, ada_w, ffada_w);
    emb_reduce_kernel<<<192, 256>>>(ada_b, ffada_b);

    // 2. pack/convert weights to bf16
    {
        long total = 4L * 1024 * 2048 + 3072;
        int blocks = (int)((total + 255) / 256);
        pack_kernel<<<blocks, 256>>>(ssm_w1, bwd_w1, ssm_w2, bwd_w2, ff_w1, ff_w2,
                                     ssm_b1, bwd_b1, ssm_b2, bwd_b2);
    }

    // 3. LN1 + modulation + mask -> norm (bf16)   [warp-per-row: 2048 blocks]
    ln_mod_kernel<<<MTOK / 8, 256>>>(x, emb, mask, norm, 1);

    // 4. hcat = gelu_erf(norm @ Wcat1 + bcat1)        [M,2048]
    gemm_bf16<0><<<dim3(DFF / GBN, MTOK / GBM), 256, SMEM_DYN>>>(
        norm, (const __nv_bfloat16*)p_w1, (const float*)p_b1, DFF, DDIM,
        nullptr, nullptr, nullptr, nullptr, hcat);

    // 5. x2 = x + gate_msa * mask * (hcat @ Wcat2 + bcat2)   [M,1024] fp32
    gemm_bf16<1><<<dim3(DDIM / GBN, MTOK / GBM), 256, SMEM_DYN>>>(
        hcat, (const __nv_bfloat16*)p_w2, (const float*)p_b2, DDIM, DFF,
        x, emb + 2048, mask, x2, nullptr);

    // 6. LN2 + modulation (no mask) -> norm reused (bf16)
    ln_mod_kernel<<<MTOK / 8, 256>>>(x2, emb + 8 * 3072, nullptr, norm, 0);

    // 7. h = gelu_tanh(norm @ ff_w1 + ff_b1)          [M,2048]
    gemm_bf16<2><<<dim3(DFF / GBN, MTOK / GBM), 256, SMEM_DYN>>>(
        norm, (const __nv_bfloat16*)p_fw1, ff_b1, DFF, DDIM,
        nullptr, nullptr, nullptr, nullptr, hcat);

    // 8. out = x2 + gate_mlp * (h @ ff_w2 + ff_b2)    [M,1024] fp32 -> d_out
    gemm_bf16<3><<<dim3(DDIM / GBN, MTOK / GBM), 256, SMEM_DYN>>>(
        hcat, (const __nv_bfloat16*)p_fw2, ff_b2, DDIM, DFF,
        x2, emb + 8 * 3072 + 2048, nullptr, (float*)d_out, nullptr);
}

// round 14
// speedup vs baseline: 1.0663x; 1.0663x over previous
#include <cuda_runtime.h>
#include <cuda_bf16.h>
#include <cstdint>

// ============================================================================
// B=8, L=2048, D=1024, FF_MULT=2  ->  M = 16384 tokens
// Flips cancel; fwd+bwd fused into one wide MLP. 4 bf16 mma.sync GEMMs
// (toolchain compiles via compute_100: no tcgen05/'a' features available).
// GEMM: r12 config (BM=128,BN=128,BK=32, 3-stage single-sync ring, warp tile
// 64x32, per-ks fragment loads). LN: warp-per-row (r13-measured WIN, 31.6->23.7us).
// Closed directions: BK=64 (r4/5,r9), BN=64/3CTA (r11), warp-shape swap
// (r12 neutral), afr-upfront batching (r4 AND r13 both regressed).
// ============================================================================

#define MTOK   16384
#define DDIM   1024
#define DFF    2048

// --------------------------- scratch (static device globals) ----------------
__device__ __nv_bfloat16 g_norm [ (size_t)MTOK * DDIM ];
__device__ __nv_bfloat16 g_hcat [ (size_t)MTOK * DFF  ];
__device__ float          g_x2  [ (size_t)MTOK * DDIM ];
__device__ __nv_bfloat16 g_wcat1[ (size_t)DDIM * DFF ];    // [1024,2048]
__device__ __nv_bfloat16 g_wcat2[ (size_t)DFF * DDIM ];    // [2048,1024]
__device__ __nv_bfloat16 g_ffw1 [ (size_t)DDIM * DFF ];
__device__ __nv_bfloat16 g_ffw2 [ (size_t)DFF * DDIM ];
__device__ float          g_emb [ 2 * 8 * 3072 ];
__device__ float          g_emb_part[8 * 6144 * 8];        // [kz][cg][b]
__device__ float          g_bcat1[DFF];
__device__ float          g_bcat2[DDIM];

// --------------------------- small helpers ----------------------------------
__device__ __forceinline__ float gelu_erf_f(float x)  { return 0.5f * x * (1.0f + erff(x * 0.70710678118654752f)); }
__device__ __forceinline__ float gelu_tanh_f(float x) {
    float x3 = x * x * x;
    return 0.5f * x * (1.0f + tanhf(0.7978845608028654f * (x + 0.044715f * x3)));
}

__device__ __forceinline__ void cp_async16(void* smem_ptr, const void* gptr) {
    uint32_t s = (uint32_t)__cvta_generic_to_shared(smem_ptr);
    asm volatile("cp.async.cg.shared.global [%0], [%1], 16;\n" :: "r"(s), "l"(gptr));
}
#define CP_COMMIT() asm volatile("cp.async.commit_group;\n" ::)
#define CP_WAIT(N_) asm volatile("cp.async.wait_group %0;\n" :: "n"(N_))

__device__ __forceinline__ void ldsm_x4(uint32_t* r, const void* p) {
    uint32_t a = (uint32_t)__cvta_generic_to_shared(p);
    asm volatile("ldmatrix.sync.aligned.m8n8.x4.shared.b16 {%0,%1,%2,%3}, [%4];"
                 : "=r"(r[0]), "=r"(r[1]), "=r"(r[2]), "=r"(r[3]) : "r"(a));
}
__device__ __forceinline__ void ldsm_x4_t(uint32_t* r, const void* p) {
    uint32_t a = (uint32_t)__cvta_generic_to_shared(p);
    asm volatile("ldmatrix.sync.aligned.m8n8.x4.trans.shared.b16 {%0,%1,%2,%3}, [%4];"
                 : "=r"(r[0]), "=r"(r[1]), "=r"(r[2]), "=r"(r[3]) : "r"(a));
}
__device__ __forceinline__ void mma16816(float* c, const uint32_t* a, uint32_t b0, uint32_t b1) {
    asm volatile("mma.sync.aligned.m16n8k16.row.col.f32.bf16.bf16.f32 "
                 "{%0,%1,%2,%3}, {%4,%5,%6,%7}, {%8,%9}, {%0,%1,%2,%3};"
                 : "+f"(c[0]), "+f"(c[1]), "+f"(c[2]), "+f"(c[3])
                 : "r"(a[0]), "r"(a[1]), "r"(a[2]), "r"(a[3]), "r"(b0), "r"(b1));
}

// --------------------------- adaLN embedding: split-K two-phase --------------
__global__ __launch_bounds__(256) void emb_part_kernel(
    const float* __restrict__ t,
    const float* __restrict__ ada_w, const float* __restrict__ ffada_w)
{
    __shared__ float st[8][128];
    const int tid = threadIdx.x;
    const int kz  = blockIdx.y;
    const int k0  = kz * 128;
    for (int i = tid; i < 8 * 128; i += 256) {
        int b = i >> 7, kk = i & 127;
        float tv = t[b * 1024 + k0 + kk];
        st[b][kk] = tv / (1.0f + expf(-tv));
    }
    __syncthreads();

    const int cg = blockIdx.x * 256 + tid;          // 0..6143
    const float* w = (cg < 3072) ? ada_w : ffada_w;
    const int col  = (cg < 3072) ? cg : cg - 3072;

    float acc[8];
#pragma unroll
    for (int b = 0; b < 8; ++b) acc[b] = 0.0f;
#pragma unroll 4
    for (int k = 0; k < 128; ++k) {
        float wv = w[(size_t)(k0 + k) * 3072 + col];
#pragma unroll
        for (int b = 0; b < 8; ++b) acc[b] += st[b][k] * wv;
    }
    float* out = g_emb_part + ((size_t)kz * 6144 + cg) * 8;
#pragma unroll
    for (int b = 0; b < 8; ++b) out[b] = acc[b];
}

__global__ __launch_bounds__(256) void emb_reduce_kernel(
    const float* __restrict__ ada_b, const float* __restrict__ ffada_b)
{
    int idx = blockIdx.x * 256 + threadIdx.x;       // 0..49151
    int cg = idx >> 3, b = idx & 7;
    float s = 0.f;
#pragma unroll
    for (int kz = 0; kz < 8; ++kz)
        s += g_emb_part[((size_t)kz * 6144 + cg) * 8 + b];
    if (cg < 3072) g_emb[b * 3072 + cg] = s + ada_b[cg];
    else           g_emb[8 * 3072 + b * 3072 + (cg - 3072)] = s + ffada_b[cg - 3072];
}

// --------------------------- weight pack / convert ---------------------------
__global__ __launch_bounds__(256) void pack_kernel(
    const float* __restrict__ ssm_w1, const float* __restrict__ bwd_w1,
    const float* __restrict__ ssm_w2, const float* __restrict__ bwd_w2,
    const float* __restrict__ ff_w1,  const float* __restrict__ ff_w2,
    const float* __restrict__ ssm_b1, const float* __restrict__ bwd_b1,
    const float* __restrict__ ssm_b2, const float* __restrict__ bwd_b2)
{
    const long W = (long)1024 * 2048;
    long i = (long)blockIdx.x * 256 + threadIdx.x;
    const long total = 4 * W + 3072;
    if (i >= total) return;

    if (i < W) {
        int k = (int)(i >> 11), j = (int)(i & 2047);
        float v = (j < 1024) ? ssm_w1[(size_t)k * 1024 + j]
                             : bwd_w1[(size_t)k * 1024 + (j - 1024)];
        g_wcat1[i] = __float2bfloat16(v);
    } else if (i < 2 * W) {
        long q = i - W;
        int k = (int)(q >> 10), j = (int)(q & 1023);
        float v = (k < 1024) ? ssm_w2[(size_t)k * 1024 + j]
                             : bwd_w2[(size_t)(k - 1024) * 1024 + j];
        g_wcat2[q] = __float2bfloat16(v);
    } else if (i < 3 * W) {
        long q = i - 2 * W;
        g_ffw1[q] = __float2bfloat16(ff_w1[q]);
    } else if (i < 4 * W) {
        long q = i - 3 * W;
        g_ffw2[q] = __float2bfloat16(ff_w2[q]);
    } else {
        long q = i - 4 * W;
        if (q < 2048) g_bcat1[q] = (q < 1024) ? ssm_b1[q] : bwd_b1[q - 1024];
        else          g_bcat2[q - 2048] = ssm_b2[q - 2048] + bwd_b2[q - 2048];
    }
}

// --------------------------- layernorm + adaLN modulation --------------------
// Warp-per-row (r13 WIN: 31.6->23.7us): 8 warps/block = 8 rows/block, zero
// block barriers, 8 float4 loads/thread (MLP=8), butterfly shuffle reduction.
__global__ __launch_bounds__(256) void ln_mod_kernel(
    const float* __restrict__ X, const float* __restrict__ embp,
    const int* __restrict__ mask, __nv_bfloat16* __restrict__ out, int use_mask)
{
    const int warp = threadIdx.x >> 5, lane = threadIdx.x & 31;
    const int row  = blockIdx.x * 8 + warp;
    const int b    = row >> 11;

    const float4* xr = reinterpret_cast<const float4*>(X + (size_t)row * 1024);
    float4 v[8];
    float s = 0.f, s2 = 0.f;
#pragma unroll
    for (int i = 0; i < 8; ++i) {
        v[i] = xr[lane + 32 * i];
        s  += v[i].x + v[i].y + v[i].z + v[i].w;
        s2 += v[i].x * v[i].x + v[i].y * v[i].y + v[i].z * v[i].z + v[i].w * v[i].w;
    }
#pragma unroll
    for (int off = 16; off > 0; off >>= 1) {
        s  += __shfl_xor_sync(0xffffffffu, s,  off);
        s2 += __shfl_xor_sync(0xffffffffu, s2, off);
    }
    const float mu   = s * (1.0f / 1024.0f);
    const float rstd = rsqrtf(s2 * (1.0f / 1024.0f) - mu * mu + 1e-6f);

    const int mk = use_mask ? mask[row] : 1;
    const float* eb = embp + b * 3072;
#pragma unroll
    for (int i = 0; i < 8; ++i) {
        const int d0 = (lane + 32 * i) * 4;
        float vv[4] = {v[i].x, v[i].y, v[i].z, v[i].w};
        union { __nv_bfloat16 o[4]; uint2 u; } pack;
#pragma unroll
        for (int q = 0; q < 4; ++q) {
            int d = d0 + q;
            float y = mk ? ((vv[q] - mu) * rstd * (1.0f + eb[1024 + d]) + eb[d]) : 0.0f;
            pack.o[q] = __float2bfloat16(y);
        }
        *reinterpret_cast<uint2*>(out + (size_t)row * 1024 + d0) = pack.u;
    }
}

// --------------------------- bf16 GEMM with fused epilogues ------------------
// r12-verified config. C[M,N] = A[M,K] @ B[K,N]. BM=128, BN=128, BK=32,
// 3-stage single-sync cp.async ring, warp grid 2m x 4n (tile 64x32),
// per-ks fragment loads (afr 16 + bfr 8 regs live). 2 CTAs/SM (128-reg cap).
// Rows padded to odd 16B-unit strides (A:80B=5u, B:272B=17u) -> conflict-free.
// MODE 0: bf16=gelu_erf(acc+bias)  MODE 2: bf16=gelu_tanh(acc+bias)
// MODE 1: f32=res+gate*(mask?acc+bias:0)  MODE 3: f32=res+gate*(acc+bias)
#define GBM 128
#define GBN 128
#define GBK 32
#define A_ROW_B   80                       // 40 bf16 = 5 x 16B (odd)
#define B_ROW_B   272                      // 136 bf16 = 17 x 16B (odd)
#define A_STAGE_B (GBM * A_ROW_B)          // 10240
#define B_STAGE_B (GBK * B_ROW_B)          // 8704
#define STAGE_B   (A_STAGE_B + B_STAGE_B)  // 18944
#define SMEM_DYN  (3 * STAGE_B)            // 56832

template <int MODE>
__global__ __launch_bounds__(256, 2) void gemm_bf16(
    const __nv_bfloat16* __restrict__ A, const __nv_bfloat16* __restrict__ Bw,
    const float* __restrict__ bias, int N, int K,
    const float* __restrict__ res, const float* __restrict__ gate_base,
    const int* __restrict__ mask,
    float* __restrict__ outf, __nv_bfloat16* __restrict__ outb)
{
    extern __shared__ __align__(16) char sm[];

    const int tid  = threadIdx.x;
    const int warp = tid >> 5, lane = tid & 31;
    const int wm = warp >> 2, wn = warp & 3;        // 2m x 4n warps, tile 64x32
    const int bm = blockIdx.y * GBM;
    const int bn = blockIdx.x * GBN;
    const int KT = K / GBK;

    float acc[4][4][4];                             // [m-frag][n8-frag][reg]
#pragma unroll
    for (int i = 0; i < 4; ++i)
#pragma unroll
        for (int j = 0; j < 4; ++j)
#pragma unroll
            for (int q = 0; q < 4; ++q) acc[i][j][q] = 0.0f;

    // loaders: A 64 rows/pass x 32 cols; B 16 rows/pass x 128 cols
    const int ar = tid >> 2, ac = (tid & 3) * 8;
    const int br = tid >> 4, bc = (tid & 15) * 8;

    auto a_ptr = [&](int s, int r, int c) -> char* {
        return sm + s * STAGE_B + r * A_ROW_B + c * 2;
    };
    auto b_ptr = [&](int s, int r, int c) -> char* {
        return sm + s * STAGE_B + A_STAGE_B + r * B_ROW_B + c * 2;
    };

    auto load_stage = [&](int s, int kt) {
        const int k0 = kt * GBK;
#pragma unroll
        for (int rr = 0; rr < 2; ++rr)
            cp_async16(a_ptr(s, ar + rr * 64, ac),
                       A + (size_t)(bm + ar + rr * 64) * K + k0 + ac);
#pragma unroll
        for (int rr = 0; rr < 2; ++rr)
            cp_async16(b_ptr(s, br + rr * 16, bc),
                       Bw + (size_t)(k0 + br + rr * 16) * N + bn + bc);
        CP_COMMIT();
    };

    load_stage(0, 0);
    load_stage(1, 1);

    const int arow0 = wm * 64 + (lane & 15);
    const int hi8   = ((lane >> 4) & 1) << 3;
    const int brow0 = lane & 15;

    for (int kt = 0; kt < KT; ++kt) {
        const int s = kt % 3;
        if (kt + 1 < KT) CP_WAIT(1); else CP_WAIT(0);
        __syncthreads();
        if (kt + 2 < KT) load_stage((kt + 2) % 3, kt + 2);

#pragma unroll
        for (int ks = 0; ks < GBK; ks += 16) {
            uint32_t afr[4][4], bfr[2][4];
#pragma unroll
            for (int i = 0; i < 4; ++i)
                ldsm_x4(afr[i], a_ptr(s, arow0 + i * 16, ks + hi8));
            const int brow = ks + brow0;
#pragma unroll
            for (int j = 0; j < 2; ++j)
                ldsm_x4_t(bfr[j], b_ptr(s, brow, wn * 32 + j * 16 + hi8));
#pragma unroll
            for (int i = 0; i < 4; ++i)
#pragma unroll
                for (int j = 0; j < 2; ++j) {
                    mma16816(acc[i][2 * j + 0], afr[i], bfr[j][0], bfr[j][1]);
                    mma16816(acc[i][2 * j + 1], afr[i], bfr[j][2], bfr[j][3]);
                }
        }
    }

    // ------------------------------ epilogue ------------------------------
#pragma unroll
    for (int i = 0; i < 4; ++i) {
#pragma unroll
        for (int j = 0; j < 4; ++j) {
            const int mrow0 = bm + wm * 64 + i * 16 + (lane >> 2);
            const int ncol  = bn + wn * 32 + j * 8 + (lane & 3) * 2;
#pragma unroll
            for (int h = 0; h < 2; ++h) {
                const int row = mrow0 + h * 8;
                float v0 = acc[i][j][h * 2 + 0] + bias[ncol];
                float v1 = acc[i][j][h * 2 + 1] + bias[ncol + 1];
                if constexpr (MODE == 0 || MODE == 2) {
                    if constexpr (MODE == 0) { v0 = gelu_erf_f(v0);  v1 = gelu_erf_f(v1); }
                    else                     { v0 = gelu_tanh_f(v0); v1 = gelu_tanh_f(v1); }
                    __nv_bfloat162 p;
                    p.x = __float2bfloat16(v0);
                    p.y = __float2bfloat16(v1);
                    *reinterpret_cast<__nv_bfloat162*>(outb + (size_t)row * N + ncol) = p;
                } else {
                    const int b = row >> 11;
                    if constexpr (MODE == 1) {
                        if (!mask[row]) { v0 = 0.0f; v1 = 0.0f; }
                    }
                    const float g0 = gate_base[b * 3072 + ncol];
                    const float g1 = gate_base[b * 3072 + ncol + 1];
                    float2 r;
                    r.x = res[(size_t)row * N + ncol]     + g0 * v0;
                    r.y = res[(size_t)row * N + ncol + 1] + g1 * v1;
                    *reinterpret_cast<float2*>(outf + (size_t)row * N + ncol) = r;
                }
            }
        }
    }
}

// --------------------------- launch ------------------------------------------
extern "C" void kernel_launch(void* const* d_in, const int* in_sizes, int n_in,
                              void* d_out, int out_size)
{
    const float* x       = (const float*)d_in[0];
    const float* t       = (const float*)d_in[1];
    const int*   mask    = (const int*)  d_in[2];
    const float* ada_w   = (const float*)d_in[3];
    const float* ada_b   = (const float*)d_in[4];
    const float* ssm_w1  = (const float*)d_in[5];
    const float* ssm_b1  = (const float*)d_in[6];
    const float* ssm_w2  = (const float*)d_in[7];
    const float* ssm_b2  = (const float*)d_in[8];
    const float* bwd_w1  = (const float*)d_in[9];
    const float* bwd_b1  = (const float*)d_in[10];
    const float* bwd_w2  = (const float*)d_in[11];
    const float* bwd_b2  = (const float*)d_in[12];
    const float* ffada_w = (const float*)d_in[13];
    const float* ffada_b = (const float*)d_in[14];
    const float* ff_w1   = (const float*)d_in[15];
    const float* ff_b1   = (const float*)d_in[16];
    const float* ff_w2   = (const float*)d_in[17];
    const float* ff_b2   = (const float*)d_in[18];

    void *p_norm, *p_hcat, *p_x2, *p_w1, *p_w2, *p_fw1, *p_fw2, *p_emb, *p_b1, *p_b2;
    cudaGetSymbolAddress(&p_norm, g_norm);
    cudaGetSymbolAddress(&p_hcat, g_hcat);
    cudaGetSymbolAddress(&p_x2,   g_x2);
    cudaGetSymbolAddress(&p_w1,   g_wcat1);
    cudaGetSymbolAddress(&p_w2,   g_wcat2);
    cudaGetSymbolAddress(&p_fw1,  g_ffw1);
    cudaGetSymbolAddress(&p_fw2,  g_ffw2);
    cudaGetSymbolAddress(&p_emb,  g_emb);
    cudaGetSymbolAddress(&p_b1,   g_bcat1);
    cudaGetSymbolAddress(&p_b2,   g_bcat2);

    __nv_bfloat16* norm = (__nv_bfloat16*)p_norm;
    __nv_bfloat16* hcat = (__nv_bfloat16*)p_hcat;
    float*         x2   = (float*)p_x2;
    float*         emb  = (float*)p_emb;

    cudaFuncSetAttribute(gemm_bf16<0>, cudaFuncAttributeMaxDynamicSharedMemorySize, SMEM_DYN);
    cudaFuncSetAttribute(gemm_bf16<1>, cudaFuncAttributeMaxDynamicSharedMemorySize, SMEM_DYN);
    cudaFuncSetAttribute(gemm_bf16<2>, cudaFuncAttributeMaxDynamicSharedMemorySize, SMEM_DYN);
    cudaFuncSetAttribute(gemm_bf16<3>, cudaFuncAttributeMaxDynamicSharedMemorySize, SMEM_DYN);

    // 1. adaLN embeddings (split-K two-phase)
    emb_part_kernel<<<dim3(24, 8), 256>>>(t, ada_w, ffada_w);
    emb_reduce_kernel<<<192, 256>>>(ada_b, ffada_b);

    // 2. pack/convert weights to bf16
    {
        long total = 4L * 1024 * 2048 + 3072;
        int blocks = (int)((total + 255) / 256);
        pack_kernel<<<blocks, 256>>>(ssm_w1, bwd_w1, ssm_w2, bwd_w2, ff_w1, ff_w2,
                                     ssm_b1, bwd_b1, ssm_b2, bwd_b2);
    }

    // 3. LN1 + modulation + mask -> norm (bf16)   [warp-per-row: 2048 blocks]
    ln_mod_kernel<<<MTOK / 8, 256>>>(x, emb, mask, norm, 1);

    // 4. hcat = gelu_erf(norm @ Wcat1 + bcat1)        [M,2048]
    gemm_bf16<0><<<dim3(DFF / GBN, MTOK / GBM), 256, SMEM_DYN>>>(
        norm, (const __nv_bfloat16*)p_w1, (const float*)p_b1, DFF, DDIM,
        nullptr, nullptr, nullptr, nullptr, hcat);

    // 5. x2 = x + gate_msa * mask * (hcat @ Wcat2 + bcat2)   [M,1024] fp32
    gemm_bf16<1><<<dim3(DDIM / GBN, MTOK / GBM), 256, SMEM_DYN>>>(
        hcat, (const __nv_bfloat16*)p_w2, (const float*)p_b2, DDIM, DFF,
        x, emb + 2048, mask, x2, nullptr);

    // 6. LN2 + modulation (no mask) -> norm reused (bf16)
    ln_mod_kernel<<<MTOK / 8, 256>>>(x2, emb + 8 * 3072, nullptr, norm, 0);

    // 7. h = gelu_tanh(norm @ ff_w1 + ff_b1)          [M,2048]
    gemm_bf16<2><<<dim3(DFF / GBN, MTOK / GBM), 256, SMEM_DYN>>>(
        norm, (const __nv_bfloat16*)p_fw1, ff_b1, DFF, DDIM,
        nullptr, nullptr, nullptr, nullptr, hcat);

    // 8. out = x2 + gate_mlp * (h @ ff_w2 + ff_b2)    [M,1024] fp32 -> d_out
    gemm_bf16<3><<<dim3(DDIM / GBN, MTOK / GBM), 256, SMEM_DYN>>>(
        hcat, (const __nv_bfloat16*)p_fw2, ff_b2, DDIM, DFF,
        x2, emb + 8 * 3072 + 2048, nullptr, (float*)d_out, nullptr);
}

// round 16
// speedup vs baseline: 1.2396x; 1.1625x over previous
#include <cuda_runtime.h>
#include <cuda_bf16.h>
#include <cstdint>

// ============================================================================
// B=8, L=2048, D=1024, FF_MULT=2  ->  M = 16384 tokens
// Flips cancel; fwd+bwd fused into one wide MLP. 4 bf16 mma.sync GEMMs
// (toolchain compiles via compute_100: no tcgen05/'a' features available).
// Mask-aware row compaction: ~50% of rows are masked; for those x2 = x
// exactly (ssm branch contributes 0). GEMM-0/1 run on compacted unmasked rows
// only (order-preserving prefix scan -> deterministic); CTAs past the dynamic
// row count early-exit (fixed grid -> graph-capturable).
// GEMM core = r12/r14 verified config. LN = warp-per-row (r13 win).
// Closed: BK=64, BN=64/3CTA, warp-shape swap, afr-upfront batching.
// ============================================================================

#define MTOK   16384
#define DDIM   1024
#define DFF    2048

// --------------------------- scratch (static device globals) ----------------
__device__ __nv_bfloat16 g_norm [ (size_t)MTOK * DDIM ];
__device__ __nv_bfloat16 g_hcat [ (size_t)MTOK * DFF  ];
__device__ float          g_x2  [ (size_t)MTOK * DDIM ];
__device__ __nv_bfloat16 g_wcat1[ (size_t)DDIM * DFF ];    // [1024,2048]
__device__ __nv_bfloat16 g_wcat2[ (size_t)DFF * DDIM ];    // [2048,1024]
__device__ __nv_bfloat16 g_ffw1 [ (size_t)DDIM * DFF ];
__device__ __nv_bfloat16 g_ffw2 [ (size_t)DFF * DDIM ];
__device__ float          g_emb [ 2 * 8 * 3072 ];
__device__ float          g_emb_part[8 * 6144 * 8];        // [kz][cg][b]
__device__ float          g_bcat1[DFF];
__device__ float          g_bcat2[DDIM];
__device__ int            g_cnt[2];                        // [count, countPad128]
__device__ int            g_pos [MTOK];                    // row -> compact pos
__device__ int            g_ridx[MTOK];                    // compact pos -> row

// --------------------------- small helpers ----------------------------------
__device__ __forceinline__ float gelu_erf_f(float x)  { return 0.5f * x * (1.0f + erff(x * 0.70710678118654752f)); }
__device__ __forceinline__ float gelu_tanh_f(float x) {
    float x3 = x * x * x;
    return 0.5f * x * (1.0f + tanhf(0.7978845608028654f * (x + 0.044715f * x3)));
}

__device__ __forceinline__ void cp_async16(void* smem_ptr, const void* gptr) {
    uint32_t s = (uint32_t)__cvta_generic_to_shared(smem_ptr);
    asm volatile("cp.async.cg.shared.global [%0], [%1], 16;\n" :: "r"(s), "l"(gptr));
}
#define CP_COMMIT() asm volatile("cp.async.commit_group;\n" ::)
#define CP_WAIT(N_) asm volatile("cp.async.wait_group %0;\n" :: "n"(N_))

__device__ __forceinline__ void ldsm_x4(uint32_t* r, const void* p) {
    uint32_t a = (uint32_t)__cvta_generic_to_shared(p);
    asm volatile("ldmatrix.sync.aligned.m8n8.x4.shared.b16 {%0,%1,%2,%3}, [%4];"
                 : "=r"(r[0]), "=r"(r[1]), "=r"(r[2]), "=r"(r[3]) : "r"(a));
}
__device__ __forceinline__ void ldsm_x4_t(uint32_t* r, const void* p) {
    uint32_t a = (uint32_t)__cvta_generic_to_shared(p);
    asm volatile("ldmatrix.sync.aligned.m8n8.x4.trans.shared.b16 {%0,%1,%2,%3}, [%4];"
                 : "=r"(r[0]), "=r"(r[1]), "=r"(r[2]), "=r"(r[3]) : "r"(a));
}
__device__ __forceinline__ void mma16816(float* c, const uint32_t* a, uint32_t b0, uint32_t b1) {
    asm volatile("mma.sync.aligned.m16n8k16.row.col.f32.bf16.bf16.f32 "
                 "{%0,%1,%2,%3}, {%4,%5,%6,%7}, {%8,%9}, {%0,%1,%2,%3};"
                 : "+f"(c[0]), "+f"(c[1]), "+f"(c[2]), "+f"(c[3])
                 : "r"(a[0]), "r"(a[1]), "r"(a[2]), "r"(a[3]), "r"(b0), "r"(b1));
}

// --------------------------- mask prefix scan (order-preserving) -------------
// 1 block x 1024 threads, 16 rows/thread. Exclusive positions + total count.
__global__ __launch_bounds__(1024) void scan_kernel(const int* __restrict__ mask) {
    __shared__ int sums[1024];
    const int t = threadIdx.x;
    const int base = t * 16;
    int loc[16];
    int s = 0;
#pragma unroll
    for (int i = 0; i < 16; ++i) { loc[i] = s; s += (mask[base + i] != 0); }
    sums[t] = s;
    __syncthreads();
    for (int off = 1; off < 1024; off <<= 1) {
        int v = (t >= off) ? sums[t - off] : 0;
        __syncthreads();
        sums[t] += v;
        __syncthreads();
    }
    const int excl = sums[t] - s;
#pragma unroll
    for (int i = 0; i < 16; ++i)
        if (mask[base + i] != 0) g_pos[base + i] = excl + loc[i];
    if (t == 1023) {
        int cnt = sums[1023];
        g_cnt[0] = cnt;
        g_cnt[1] = (cnt + 127) & ~127;
    }
}

// Zero-pad compact norm rows [count, countPad). 128 blocks x 256 threads.
__global__ __launch_bounds__(256) void zero_pad_kernel() {
    const int row = g_cnt[0] + blockIdx.x;
    if (row >= g_cnt[1]) return;
    uint2* p = reinterpret_cast<uint2*>(g_norm + (size_t)row * 1024);
    uint2 z = {0u, 0u};
    p[threadIdx.x] = z;   // 256 threads x 8B = 2048B = full row
}

// x2 = x for masked rows (their ssm contribution is exactly 0). Warp-per-row.
__global__ __launch_bounds__(256) void mask_copy_kernel(
    const float* __restrict__ X, const int* __restrict__ mask, float* __restrict__ X2)
{
    const int warp = threadIdx.x >> 5, lane = threadIdx.x & 31;
    const int row = blockIdx.x * 8 + warp;
    if (mask[row]) return;
    const float4* src = reinterpret_cast<const float4*>(X  + (size_t)row * 1024);
    float4*       dst = reinterpret_cast<float4*>(X2 + (size_t)row * 1024);
#pragma unroll
    for (int i = 0; i < 8; ++i) dst[lane + 32 * i] = src[lane + 32 * i];
}

// --------------------------- adaLN embedding: split-K two-phase --------------
__global__ __launch_bounds__(256) void emb_part_kernel(
    const float* __restrict__ t,
    const float* __restrict__ ada_w, const float* __restrict__ ffada_w)
{
    __shared__ float st[8][128];
    const int tid = threadIdx.x;
    const int kz  = blockIdx.y;
    const int k0  = kz * 128;
    for (int i = tid; i < 8 * 128; i += 256) {
        int b = i >> 7, kk = i & 127;
        float tv = t[b * 1024 + k0 + kk];
        st[b][kk] = tv / (1.0f + expf(-tv));
    }
    __syncthreads();

    const int cg = blockIdx.x * 256 + tid;
    const float* w = (cg < 3072) ? ada_w : ffada_w;
    const int col  = (cg < 3072) ? cg : cg - 3072;

    float acc[8];
#pragma unroll
    for (int b = 0; b < 8; ++b) acc[b] = 0.0f;
#pragma unroll 4
    for (int k = 0; k < 128; ++k) {
        float wv = w[(size_t)(k0 + k) * 3072 + col];
#pragma unroll
        for (int b = 0; b < 8; ++b) acc[b] += st[b][k] * wv;
    }
    float* out = g_emb_part + ((size_t)kz * 6144 + cg) * 8;
#pragma unroll
    for (int b = 0; b < 8; ++b) out[b] = acc[b];
}

__global__ __launch_bounds__(256) void emb_reduce_kernel(
    const float* __restrict__ ada_b, const float* __restrict__ ffada_b)
{
    int idx = blockIdx.x * 256 + threadIdx.x;
    int cg = idx >> 3, b = idx & 7;
    float s = 0.f;
#pragma unroll
    for (int kz = 0; kz < 8; ++kz)
        s += g_emb_part[((size_t)kz * 6144 + cg) * 8 + b];
    if (cg < 3072) g_emb[b * 3072 + cg] = s + ada_b[cg];
    else           g_emb[8 * 3072 + b * 3072 + (cg - 3072)] = s + ffada_b[cg - 3072];
}

// --------------------------- weight pack / convert ---------------------------
__global__ __launch_bounds__(256) void pack_kernel(
    const float* __restrict__ ssm_w1, const float* __restrict__ bwd_w1,
    const float* __restrict__ ssm_w2, const float* __restrict__ bwd_w2,
    const float* __restrict__ ff_w1,  const float* __restrict__ ff_w2,
    const float* __restrict__ ssm_b1, const float* __restrict__ bwd_b1,
    const float* __restrict__ ssm_b2, const float* __restrict__ bwd_b2)
{
    const long W = (long)1024 * 2048;
    long i = (long)blockIdx.x * 256 + threadIdx.x;
    const long total = 4 * W + 3072;
    if (i >= total) return;

    if (i < W) {
        int k = (int)(i >> 11), j = (int)(i & 2047);
        float v = (j < 1024) ? ssm_w1[(size_t)k * 1024 + j]
                             : bwd_w1[(size_t)k * 1024 + (j - 1024)];
        g_wcat1[i] = __float2bfloat16(v);
    } else if (i < 2 * W) {
        long q = i - W;
        int k = (int)(q >> 10), j = (int)(q & 1023);
        float v = (k < 1024) ? ssm_w2[(size_t)k * 1024 + j]
                             : bwd_w2[(size_t)(k - 1024) * 1024 + j];
        g_wcat2[q] = __float2bfloat16(v);
    } else if (i < 3 * W) {
        long q = i - 2 * W;
        g_ffw1[q] = __float2bfloat16(ff_w1[q]);
    } else if (i < 4 * W) {
        long q = i - 3 * W;
        g_ffw2[q] = __float2bfloat16(ff_w2[q]);
    } else {
        long q = i - 4 * W;
        if (q < 2048) g_bcat1[q] = (q < 1024) ? ssm_b1[q] : bwd_b1[q - 1024];
        else          g_bcat2[q - 2048] = ssm_b2[q - 2048] + bwd_b2[q - 2048];
    }
}

// --------------------------- layernorm + adaLN modulation --------------------
// Warp-per-row (r13 win). COMPACT=1: skip masked rows, write unmasked rows to
// compact position g_pos[row] and record g_ridx. COMPACT=0: all rows, direct.
template <int COMPACT>
__global__ __launch_bounds__(256) void ln_mod_kernel(
    const float* __restrict__ X, const float* __restrict__ embp,
    const int* __restrict__ mask, __nv_bfloat16* __restrict__ out)
{
    const int warp = threadIdx.x >> 5, lane = threadIdx.x & 31;
    const int row  = blockIdx.x * 8 + warp;
    const int b    = row >> 11;

    int orow = row;
    if constexpr (COMPACT) {
        if (mask[row] == 0) return;
        orow = g_pos[row];
        if (lane == 0) g_ridx[orow] = row;
    }

    const float4* xr = reinterpret_cast<const float4*>(X + (size_t)row * 1024);
    float4 v[8];
    float s = 0.f, s2 = 0.f;
#pragma unroll
    for (int i = 0; i < 8; ++i) {
        v[i] = xr[lane + 32 * i];
        s  += v[i].x + v[i].y + v[i].z + v[i].w;
        s2 += v[i].x * v[i].x + v[i].y * v[i].y + v[i].z * v[i].z + v[i].w * v[i].w;
    }
#pragma unroll
    for (int off = 16; off > 0; off >>= 1) {
        s  += __shfl_xor_sync(0xffffffffu, s,  off);
        s2 += __shfl_xor_sync(0xffffffffu, s2, off);
    }
    const float mu   = s * (1.0f / 1024.0f);
    const float rstd = rsqrtf(s2 * (1.0f / 1024.0f) - mu * mu + 1e-6f);

    const float* eb = embp + b * 3072;
#pragma unroll
    for (int i = 0; i < 8; ++i) {
        const int d0 = (lane + 32 * i) * 4;
        float vv[4] = {v[i].x, v[i].y, v[i].z, v[i].w};
        union { __nv_bfloat16 o[4]; uint2 u; } pack;
#pragma unroll
        for (int q = 0; q < 4; ++q) {
            int d = d0 + q;
            float y = (vv[q] - mu) * rstd * (1.0f + eb[1024 + d]) + eb[d];
            pack.o[q] = __float2bfloat16(y);
        }
        *reinterpret_cast<uint2*>(out + (size_t)orow * 1024 + d0) = pack.u;
    }
}

// --------------------------- bf16 GEMM with fused epilogues ------------------
// r12/r14-verified core. C[M,N] = A[M,K] @ B[K,N]. BM=128, BN=128, BK=32,
// 3-stage single-sync cp.async ring, warp grid 2m x 4n (tile 64x32),
// per-ks fragment loads. 2 CTAs/SM (128-reg cap). Odd-stride padding.
// COMPACT=1: early-exit CTAs with bm >= g_cnt[1] (dynamic M, fixed grid).
// MODE 0: bf16=gelu_erf(acc+bias)          [A compact, out compact]
// MODE 1: f32[ridx]=res[ridx]+gate*(acc+bias)  [A compact, scatter via g_ridx]
// MODE 2: bf16=gelu_tanh(acc+bias)         MODE 3: f32=res+gate*(acc+bias)
#define GBM 128
#define GBN 128
#define GBK 32
#define A_ROW_B   80                       // 40 bf16 = 5 x 16B (odd)
#define B_ROW_B   272                      // 136 bf16 = 17 x 16B (odd)
#define A_STAGE_B (GBM * A_ROW_B)          // 10240
#define B_STAGE_B (GBK * B_ROW_B)          // 8704
#define STAGE_B   (A_STAGE_B + B_STAGE_B)  // 18944
#define SMEM_DYN  (3 * STAGE_B)            // 56832

template <int MODE, int COMPACT>
__global__ __launch_bounds__(256, 2) void gemm_bf16(
    const __nv_bfloat16* __restrict__ A, const __nv_bfloat16* __restrict__ Bw,
    const float* __restrict__ bias, int N, int K,
    const float* __restrict__ res, const float* __restrict__ gate_base,
    float* __restrict__ outf, __nv_bfloat16* __restrict__ outb)
{
    extern __shared__ __align__(16) char sm[];

    const int bm = blockIdx.y * GBM;
    int cnt = MTOK;
    if constexpr (COMPACT) {
        cnt = g_cnt[0];
        if (bm >= g_cnt[1]) return;
    }

    const int tid  = threadIdx.x;
    const int warp = tid >> 5, lane = tid & 31;
    const int wm = warp >> 2, wn = warp & 3;        // 2m x 4n warps, tile 64x32
    const int bn = blockIdx.x * GBN;
    const int KT = K / GBK;

    float acc[4][4][4];
#pragma unroll
    for (int i = 0; i < 4; ++i)
#pragma unroll
        for (int j = 0; j < 4; ++j)
#pragma unroll
            for (int q = 0; q < 4; ++q) acc[i][j][q] = 0.0f;

    const int ar = tid >> 2, ac = (tid & 3) * 8;
    const int br = tid >> 4, bc = (tid & 15) * 8;

    auto a_ptr = [&](int s, int r, int c) -> char* {
        return sm + s * STAGE_B + r * A_ROW_B + c * 2;
    };
    auto b_ptr = [&](int s, int r, int c) -> char* {
        return sm + s * STAGE_B + A_STAGE_B + r * B_ROW_B + c * 2;
    };

    auto load_stage = [&](int s, int kt) {
        const int k0 = kt * GBK;
#pragma unroll
        for (int rr = 0; rr < 2; ++rr)
            cp_async16(a_ptr(s, ar + rr * 64, ac),
                       A + (size_t)(bm + ar + rr * 64) * K + k0 + ac);
#pragma unroll
        for (int rr = 0; rr < 2; ++rr)
            cp_async16(b_ptr(s, br + rr * 16, bc),
                       Bw + (size_t)(k0 + br + rr * 16) * N + bn + bc);
        CP_COMMIT();
    };

    load_stage(0, 0);
    load_stage(1, 1);

    const int arow0 = wm * 64 + (lane & 15);
    const int hi8   = ((lane >> 4) & 1) << 3;
    const int brow0 = lane & 15;

    for (int kt = 0; kt < KT; ++kt) {
        const int s = kt % 3;
        if (kt + 1 < KT) CP_WAIT(1); else CP_WAIT(0);
        __syncthreads();
        if (kt + 2 < KT) load_stage((kt + 2) % 3, kt + 2);

#pragma unroll
        for (int ks = 0; ks < GBK; ks += 16) {
            uint32_t afr[4][4], bfr[2][4];
#pragma unroll
            for (int i = 0; i < 4; ++i)
                ldsm_x4(afr[i], a_ptr(s, arow0 + i * 16, ks + hi8));
            const int brow = ks + brow0;
#pragma unroll
            for (int j = 0; j < 2; ++j)
                ldsm_x4_t(bfr[j], b_ptr(s, brow, wn * 32 + j * 16 + hi8));
#pragma unroll
            for (int i = 0; i < 4; ++i)
#pragma unroll
                for (int j = 0; j < 2; ++j) {
                    mma16816(acc[i][2 * j + 0], afr[i], bfr[j][0], bfr[j][1]);
                    mma16816(acc[i][2 * j + 1], afr[i], bfr[j][2], bfr[j][3]);
                }
        }
    }

    // ------------------------------ epilogue ------------------------------
#pragma unroll
    for (int i = 0; i < 4; ++i) {
#pragma unroll
        for (int j = 0; j < 4; ++j) {
            const int mrow0 = bm + wm * 64 + i * 16 + (lane >> 2);
            const int ncol  = bn + wn * 32 + j * 8 + (lane & 3) * 2;
#pragma unroll
            for (int h = 0; h < 2; ++h) {
                const int row = mrow0 + h * 8;
                float v0 = acc[i][j][h * 2 + 0] + bias[ncol];
                float v1 = acc[i][j][h * 2 + 1] + bias[ncol + 1];
                if constexpr (MODE == 0 || MODE == 2) {
                    if constexpr (MODE == 0) { v0 = gelu_erf_f(v0);  v1 = gelu_erf_f(v1); }
                    else                     { v0 = gelu_tanh_f(v0); v1 = gelu_tanh_f(v1); }
                    __nv_bfloat162 p;
                    p.x = __float2bfloat16(v0);
                    p.y = __float2bfloat16(v1);
                    *reinterpret_cast<__nv_bfloat162*>(outb + (size_t)row * N + ncol) = p;
                } else {
                    int orow = row;
                    if constexpr (COMPACT) {
                        if (row >= cnt) continue;
                        orow = g_ridx[row];
                    }
                    const int b = orow >> 11;
                    const float g0 = gate_base[b * 3072 + ncol];
                    const float g1 = gate_base[b * 3072 + ncol + 1];
                    float2 r;
                    r.x = res[(size_t)orow * N + ncol]     + g0 * v0;
                    r.y = res[(size_t)orow * N + ncol + 1] + g1 * v1;
                    *reinterpret_cast<float2*>(outf + (size_t)orow * N + ncol) = r;
                }
            }
        }
    }
}

// --------------------------- launch ------------------------------------------
extern "C" void kernel_launch(void* const* d_in, const int* in_sizes, int n_in,
                              void* d_out, int out_size)
{
    const float* x       = (const float*)d_in[0];
    const float* t       = (const float*)d_in[1];
    const int*   mask    = (const int*)  d_in[2];
    const float* ada_w   = (const float*)d_in[3];
    const float* ada_b   = (const float*)d_in[4];
    const float* ssm_w1  = (const float*)d_in[5];
    const float* ssm_b1  = (const float*)d_in[6];
    const float* ssm_w2  = (const float*)d_in[7];
    const float* ssm_b2  = (const float*)d_in[8];
    const float* bwd_w1  = (const float*)d_in[9];
    const float* bwd_b1  = (const float*)d_in[10];
    const float* bwd_w2  = (const float*)d_in[11];
    const float* bwd_b2  = (const float*)d_in[12];
    const float* ffada_w = (const float*)d_in[13];
    const float* ffada_b = (const float*)d_in[14];
    const float* ff_w1   = (const float*)d_in[15];
    const float* ff_b1   = (const float*)d_in[16];
    const float* ff_w2   = (const float*)d_in[17];
    const float* ff_b2   = (const float*)d_in[18];

    void *p_norm, *p_hcat, *p_x2, *p_w1, *p_w2, *p_fw1, *p_fw2, *p_emb, *p_b1, *p_b2;
    cudaGetSymbolAddress(&p_norm, g_norm);
    cudaGetSymbolAddress(&p_hcat, g_hcat);
    cudaGetSymbolAddress(&p_x2,   g_x2);
    cudaGetSymbolAddress(&p_w1,   g_wcat1);
    cudaGetSymbolAddress(&p_w2,   g_wcat2);
    cudaGetSymbolAddress(&p_fw1,  g_ffw1);
    cudaGetSymbolAddress(&p_fw2,  g_ffw2);
    cudaGetSymbolAddress(&p_emb,  g_emb);
    cudaGetSymbolAddress(&p_b1,   g_bcat1);
    cudaGetSymbolAddress(&p_b2,   g_bcat2);

    __nv_bfloat16* norm = (__nv_bfloat16*)p_norm;
    __nv_bfloat16* hcat = (__nv_bfloat16*)p_hcat;
    float*         x2   = (float*)p_x2;
    float*         emb  = (float*)p_emb;

    cudaFuncSetAttribute(gemm_bf16<0,1>, cudaFuncAttributeMaxDynamicSharedMemorySize, SMEM_DYN);
    cudaFuncSetAttribute(gemm_bf16<1,1>, cudaFuncAttributeMaxDynamicSharedMemorySize, SMEM_DYN);
    cudaFuncSetAttribute(gemm_bf16<2,0>, cudaFuncAttributeMaxDynamicSharedMemorySize, SMEM_DYN);
    cudaFuncSetAttribute(gemm_bf16<3,0>, cudaFuncAttributeMaxDynamicSharedMemorySize, SMEM_DYN);

    // 1. adaLN embeddings (split-K two-phase)
    emb_part_kernel<<<dim3(24, 8), 256>>>(t, ada_w, ffada_w);
    emb_reduce_kernel<<<192, 256>>>(ada_b, ffada_b);

    // 2. pack/convert weights to bf16
    {
        long total = 4L * 1024 * 2048 + 3072;
        int blocks = (int)((total + 255) / 256);
        pack_kernel<<<blocks, 256>>>(ssm_w1, bwd_w1, ssm_w2, bwd_w2, ff_w1, ff_w2,
                                     ssm_b1, bwd_b1, ssm_b2, bwd_b2);
    }

    // 3. mask scan -> compact positions; x2 = x for masked rows
    scan_kernel<<<1, 1024>>>(mask);
    mask_copy_kernel<<<MTOK / 8, 256>>>(x, mask, x2);

    // 4. LN1 + modulation, compacted to unmasked rows
    ln_mod_kernel<1><<<MTOK / 8, 256>>>(x, emb, mask, norm);
    zero_pad_kernel<<<128, 256>>>();

    // 5. hcat_c = gelu_erf(norm_c @ Wcat1 + bcat1)    [count,2048] compact
    gemm_bf16<0,1><<<dim3(DFF / GBN, MTOK / GBM), 256, SMEM_DYN>>>(
        norm, (const __nv_bfloat16*)p_w1, (const float*)p_b1, DFF, DDIM,
        nullptr, nullptr, nullptr, hcat);

    // 6. x2[ridx] = x[ridx] + gate_msa * (hcat_c @ Wcat2 + bcat2)  scatter
    gemm_bf16<1,1><<<dim3(DDIM / GBN, MTOK / GBM), 256, SMEM_DYN>>>(
        hcat, (const __nv_bfloat16*)p_w2, (const float*)p_b2, DDIM, DFF,
        x, emb + 2048, x2, nullptr);

    // 7. LN2 + modulation (all rows)
    ln_mod_kernel<0><<<MTOK / 8, 256>>>(x2, emb + 8 * 3072, nullptr, norm);

    // 8. h = gelu_tanh(norm @ ff_w1 + ff_b1)          [M,2048]
    gemm_bf16<2,0><<<dim3(DFF / GBN, MTOK / GBM), 256, SMEM_DYN>>>(
        norm, (const __nv_bfloat16*)p_fw1, ff_b1, DFF, DDIM,
        nullptr, nullptr, nullptr, hcat);

    // 9. out = x2 + gate_mlp * (h @ ff_w2 + ff_b2)    [M,1024] fp32 -> d_out
    gemm_bf16<3,0><<<dim3(DDIM / GBN, MTOK / GBM), 256, SMEM_DYN>>>(
        hcat, (const __nv_bfloat16*)p_fw2, ff_b2, DDIM, DFF,
        x2, emb + 8 * 3072 + 2048, (float*)d_out, nullptr);
}

// round 17
// speedup vs baseline: 1.2756x; 1.0290x over previous
#include <cuda_runtime.h>
#include <cuda_bf16.h>
#include <cstdint>

// ============================================================================
// B=8, L=2048, D=1024, FF_MULT=2  ->  M = 16384 tokens
// Flips cancel; fwd+bwd fused into one wide MLP. 4 bf16 mma.sync GEMMs
// (toolchain compiles via compute_100: no tcgen05/'a' features available).
// Mask-aware row compaction (r16 win): GEMM-0/1 on compacted unmasked rows.
// r17: mask_copy fused into LN2 (masked rows: read x, store x2=x), warp-level
// scan (2 barriers), 4-stage cp.async ring probe in the GEMM.
// Closed: BK=64, BN=64/3CTA, warp-shape swap, afr-upfront batching.
// ============================================================================

#define MTOK   16384
#define DDIM   1024
#define DFF    2048

// --------------------------- scratch (static device globals) ----------------
__device__ __nv_bfloat16 g_norm [ (size_t)MTOK * DDIM ];
__device__ __nv_bfloat16 g_hcat [ (size_t)MTOK * DFF  ];
__device__ float          g_x2  [ (size_t)MTOK * DDIM ];
__device__ __nv_bfloat16 g_wcat1[ (size_t)DDIM * DFF ];    // [1024,2048]
__device__ __nv_bfloat16 g_wcat2[ (size_t)DFF * DDIM ];    // [2048,1024]
__device__ __nv_bfloat16 g_ffw1 [ (size_t)DDIM * DFF ];
__device__ __nv_bfloat16 g_ffw2 [ (size_t)DFF * DDIM ];
__device__ float          g_emb [ 2 * 8 * 3072 ];
__device__ float          g_emb_part[8 * 6144 * 8];        // [kz][cg][b]
__device__ float          g_bcat1[DFF];
__device__ float          g_bcat2[DDIM];
__device__ int            g_cnt[2];                        // [count, countPad128]
__device__ int            g_pos [MTOK];                    // row -> compact pos
__device__ int            g_ridx[MTOK];                    // compact pos -> row

// --------------------------- small helpers ----------------------------------
__device__ __forceinline__ float gelu_erf_f(float x)  { return 0.5f * x * (1.0f + erff(x * 0.70710678118654752f)); }
__device__ __forceinline__ float gelu_tanh_f(float x) {
    float x3 = x * x * x;
    return 0.5f * x * (1.0f + tanhf(0.7978845608028654f * (x + 0.044715f * x3)));
}

__device__ __forceinline__ void cp_async16(void* smem_ptr, const void* gptr) {
    uint32_t s = (uint32_t)__cvta_generic_to_shared(smem_ptr);
    asm volatile("cp.async.cg.shared.global [%0], [%1], 16;\n" :: "r"(s), "l"(gptr));
}
#define CP_COMMIT() asm volatile("cp.async.commit_group;\n" ::)
__device__ __forceinline__ void cp_wait_dyn(int n) {
    if (n <= 0)      asm volatile("cp.async.wait_group 0;\n" ::);
    else if (n == 1) asm volatile("cp.async.wait_group 1;\n" ::);
    else             asm volatile("cp.async.wait_group 2;\n" ::);
}

__device__ __forceinline__ void ldsm_x4(uint32_t* r, const void* p) {
    uint32_t a = (uint32_t)__cvta_generic_to_shared(p);
    asm volatile("ldmatrix.sync.aligned.m8n8.x4.shared.b16 {%0,%1,%2,%3}, [%4];"
                 : "=r"(r[0]), "=r"(r[1]), "=r"(r[2]), "=r"(r[3]) : "r"(a));
}
__device__ __forceinline__ void ldsm_x4_t(uint32_t* r, const void* p) {
    uint32_t a = (uint32_t)__cvta_generic_to_shared(p);
    asm volatile("ldmatrix.sync.aligned.m8n8.x4.trans.shared.b16 {%0,%1,%2,%3}, [%4];"
                 : "=r"(r[0]), "=r"(r[1]), "=r"(r[2]), "=r"(r[3]) : "r"(a));
}
__device__ __forceinline__ void mma16816(float* c, const uint32_t* a, uint32_t b0, uint32_t b1) {
    asm volatile("mma.sync.aligned.m16n8k16.row.col.f32.bf16.bf16.f32 "
                 "{%0,%1,%2,%3}, {%4,%5,%6,%7}, {%8,%9}, {%0,%1,%2,%3};"
                 : "+f"(c[0]), "+f"(c[1]), "+f"(c[2]), "+f"(c[3])
                 : "r"(a[0]), "r"(a[1]), "r"(a[2]), "r"(a[3]), "r"(b0), "r"(b1));
}

// --------------------------- mask prefix scan (warp-level, 2 barriers) -------
// 1 block x 1024 threads, 16 rows/thread.
__global__ __launch_bounds__(1024) void scan_kernel(const int* __restrict__ mask) {
    __shared__ int wsum[32];
    const int t = threadIdx.x;
    const int lane = t & 31, warp = t >> 5;
    const int base = t * 16;
    int loc[16];
    int s = 0;
#pragma unroll
    for (int i = 0; i < 16; ++i) { loc[i] = s; s += (mask[base + i] != 0); }

    // inclusive warp scan of s
    int inc = s;
#pragma unroll
    for (int off = 1; off < 32; off <<= 1) {
        int v = __shfl_up_sync(0xffffffffu, inc, off);
        if (lane >= off) inc += v;
    }
    if (lane == 31) wsum[warp] = inc;
    __syncthreads();
    if (warp == 0) {
        int w = (lane < 32) ? wsum[lane] : 0;
#pragma unroll
        for (int off = 1; off < 32; off <<= 1) {
            int v = __shfl_up_sync(0xffffffffu, w, off);
            if (lane >= off) w += v;
        }
        wsum[lane] = w;            // inclusive over warps
    }
    __syncthreads();
    const int warp_base = (warp == 0) ? 0 : wsum[warp - 1];
    const int excl = warp_base + inc - s;
#pragma unroll
    for (int i = 0; i < 16; ++i)
        if (mask[base + i] != 0) g_pos[base + i] = excl + loc[i];
    if (t == 1023) {
        int cnt = wsum[31];
        g_cnt[0] = cnt;
        g_cnt[1] = (cnt + 127) & ~127;
    }
}

// Zero-pad compact norm rows [count, countPad). 128 blocks x 256 threads.
__global__ __launch_bounds__(256) void zero_pad_kernel() {
    const int row = g_cnt[0] + blockIdx.x;
    if (row >= g_cnt[1]) return;
    uint2* p = reinterpret_cast<uint2*>(g_norm + (size_t)row * 1024);
    uint2 z = {0u, 0u};
    p[threadIdx.x] = z;
}

// --------------------------- adaLN embedding: split-K two-phase --------------
__global__ __launch_bounds__(256) void emb_part_kernel(
    const float* __restrict__ t,
    const float* __restrict__ ada_w, const float* __restrict__ ffada_w)
{
    __shared__ float st[8][128];
    const int tid = threadIdx.x;
    const int kz  = blockIdx.y;
    const int k0  = kz * 128;
    for (int i = tid; i < 8 * 128; i += 256) {
        int b = i >> 7, kk = i & 127;
        float tv = t[b * 1024 + k0 + kk];
        st[b][kk] = tv / (1.0f + expf(-tv));
    }
    __syncthreads();

    const int cg = blockIdx.x * 256 + tid;
    const float* w = (cg < 3072) ? ada_w : ffada_w;
    const int col  = (cg < 3072) ? cg : cg - 3072;

    float acc[8];
#pragma unroll
    for (int b = 0; b < 8; ++b) acc[b] = 0.0f;
#pragma unroll 4
    for (int k = 0; k < 128; ++k) {
        float wv = w[(size_t)(k0 + k) * 3072 + col];
#pragma unroll
        for (int b = 0; b < 8; ++b) acc[b] += st[b][k] * wv;
    }
    float* out = g_emb_part + ((size_t)kz * 6144 + cg) * 8;
#pragma unroll
    for (int b = 0; b < 8; ++b) out[b] = acc[b];
}

__global__ __launch_bounds__(256) void emb_reduce_kernel(
    const float* __restrict__ ada_b, const float* __restrict__ ffada_b)
{
    int idx = blockIdx.x * 256 + threadIdx.x;
    int cg = idx >> 3, b = idx & 7;
    float s = 0.f;
#pragma unroll
    for (int kz = 0; kz < 8; ++kz)
        s += g_emb_part[((size_t)kz * 6144 + cg) * 8 + b];
    if (cg < 3072) g_emb[b * 3072 + cg] = s + ada_b[cg];
    else           g_emb[8 * 3072 + b * 3072 + (cg - 3072)] = s + ffada_b[cg - 3072];
}

// --------------------------- weight pack / convert ---------------------------
__global__ __launch_bounds__(256) void pack_kernel(
    const float* __restrict__ ssm_w1, const float* __restrict__ bwd_w1,
    const float* __restrict__ ssm_w2, const float* __restrict__ bwd_w2,
    const float* __restrict__ ff_w1,  const float* __restrict__ ff_w2,
    const float* __restrict__ ssm_b1, const float* __restrict__ bwd_b1,
    const float* __restrict__ ssm_b2, const float* __restrict__ bwd_b2)
{
    const long W = (long)1024 * 2048;
    long i = (long)blockIdx.x * 256 + threadIdx.x;
    const long total = 4 * W + 3072;
    if (i >= total) return;

    if (i < W) {
        int k = (int)(i >> 11), j = (int)(i & 2047);
        float v = (j < 1024) ? ssm_w1[(size_t)k * 1024 + j]
                             : bwd_w1[(size_t)k * 1024 + (j - 1024)];
        g_wcat1[i] = __float2bfloat16(v);
    } else if (i < 2 * W) {
        long q = i - W;
        int k = (int)(q >> 10), j = (int)(q & 1023);
        float v = (k < 1024) ? ssm_w2[(size_t)k * 1024 + j]
                             : bwd_w2[(size_t)(k - 1024) * 1024 + j];
        g_wcat2[q] = __float2bfloat16(v);
    } else if (i < 3 * W) {
        long q = i - 2 * W;
        g_ffw1[q] = __float2bfloat16(ff_w1[q]);
    } else if (i < 4 * W) {
        long q = i - 3 * W;
        g_ffw2[q] = __float2bfloat16(ff_w2[q]);
    } else {
        long q = i - 4 * W;
        if (q < 2048) g_bcat1[q] = (q < 1024) ? ssm_b1[q] : bwd_b1[q - 1024];
        else          g_bcat2[q - 2048] = ssm_b2[q - 2048] + bwd_b2[q - 2048];
    }
}

// --------------------------- layernorm + adaLN modulation --------------------
// Warp-per-row (r13 win).
// MODE_LN 0: LN1 compact — skip masked rows; write norm at g_pos[row]; record ridx.
// MODE_LN 1: LN2 fused  — unmasked rows read X2; masked rows read Xalt (=x) and
//            ALSO store x2 = x (replaces the old mask_copy kernel).
template <int MODE_LN>
__global__ __launch_bounds__(256) void ln_mod_kernel(
    const float* __restrict__ X, const float* __restrict__ Xalt,
    const float* __restrict__ embp, const int* __restrict__ mask,
    __nv_bfloat16* __restrict__ out, float* __restrict__ x2store)
{
    const int warp = threadIdx.x >> 5, lane = threadIdx.x & 31;
    const int row  = blockIdx.x * 8 + warp;
    const int b    = row >> 11;

    int orow = row;
    int mk = 1;
    const float* src = X;
    if constexpr (MODE_LN == 0) {
        if (mask[row] == 0) return;
        orow = g_pos[row];
        if (lane == 0) g_ridx[orow] = row;
    } else {
        mk = mask[row];
        if (!mk) src = Xalt;             // x2 was never written for masked rows
    }

    const float4* xr = reinterpret_cast<const float4*>(src + (size_t)row * 1024);
    float4 v[8];
    float s = 0.f, s2 = 0.f;
#pragma unroll
    for (int i = 0; i < 8; ++i) {
        v[i] = xr[lane + 32 * i];
        s  += v[i].x + v[i].y + v[i].z + v[i].w;
        s2 += v[i].x * v[i].x + v[i].y * v[i].y + v[i].z * v[i].z + v[i].w * v[i].w;
    }
    if constexpr (MODE_LN == 1) {        // materialize x2 = x for masked rows
        if (!mk) {
            float4* dst = reinterpret_cast<float4*>(x2store + (size_t)row * 1024);
#pragma unroll
            for (int i = 0; i < 8; ++i) dst[lane + 32 * i] = v[i];
        }
    }
#pragma unroll
    for (int off = 16; off > 0; off >>= 1) {
        s  += __shfl_xor_sync(0xffffffffu, s,  off);
        s2 += __shfl_xor_sync(0xffffffffu, s2, off);
    }
    const float mu   = s * (1.0f / 1024.0f);
    const float rstd = rsqrtf(s2 * (1.0f / 1024.0f) - mu * mu + 1e-6f);

    const float* eb = embp + b * 3072;
#pragma unroll
    for (int i = 0; i < 8; ++i) {
        const int d0 = (lane + 32 * i) * 4;
        float vv[4] = {v[i].x, v[i].y, v[i].z, v[i].w};
        union { __nv_bfloat16 o[4]; uint2 u; } pack;
#pragma unroll
        for (int q = 0; q < 4; ++q) {
            int d = d0 + q;
            float y = (vv[q] - mu) * rstd * (1.0f + eb[1024 + d]) + eb[d];
            pack.o[q] = __float2bfloat16(y);
        }
        *reinterpret_cast<uint2*>(out + (size_t)orow * 1024 + d0) = pack.u;
    }
}

// --------------------------- bf16 GEMM with fused epilogues ------------------
// r12/r14 core + 4-stage cp.async ring probe (was 3): deeper prefetch to cover
// L2 latency. BM=128, BN=128, BK=32, single sync/iter, warp tile 64x32,
// per-ks fragment loads. 2 CTAs/SM (128-reg cap). Odd-stride padding.
// COMPACT=1: early-exit CTAs with bm >= g_cnt[1].
// MODE 0: bf16=gelu_erf(acc+bias)          [compact in/out]
// MODE 1: f32[ridx]=res[ridx]+gate*(acc+bias)  [compact A, scatter]
// MODE 2: bf16=gelu_tanh(acc+bias)         MODE 3: f32=res+gate*(acc+bias)
#define GBM 128
#define GBN 128
#define GBK 32
#define NSTG 4
#define A_ROW_B   80
#define B_ROW_B   272
#define A_STAGE_B (GBM * A_ROW_B)          // 10240
#define B_STAGE_B (GBK * B_ROW_B)          // 8704
#define STAGE_B   (A_STAGE_B + B_STAGE_B)  // 18944
#define SMEM_DYN  (NSTG * STAGE_B)         // 75776

template <int MODE, int COMPACT>
__global__ __launch_bounds__(256, 2) void gemm_bf16(
    const __nv_bfloat16* __restrict__ A, const __nv_bfloat16* __restrict__ Bw,
    const float* __restrict__ bias, int N, int K,
    const float* __restrict__ res, const float* __restrict__ gate_base,
    float* __restrict__ outf, __nv_bfloat16* __restrict__ outb)
{
    extern __shared__ __align__(16) char sm[];

    const int bm = blockIdx.y * GBM;
    int cnt = MTOK;
    if constexpr (COMPACT) {
        cnt = g_cnt[0];
        if (bm >= g_cnt[1]) return;
    }

    const int tid  = threadIdx.x;
    const int warp = tid >> 5, lane = tid & 31;
    const int wm = warp >> 2, wn = warp & 3;        // 2m x 4n warps, tile 64x32
    const int bn = blockIdx.x * GBN;
    const int KT = K / GBK;

    float acc[4][4][4];
#pragma unroll
    for (int i = 0; i < 4; ++i)
#pragma unroll
        for (int j = 0; j < 4; ++j)
#pragma unroll
            for (int q = 0; q < 4; ++q) acc[i][j][q] = 0.0f;

    const int ar = tid >> 2, ac = (tid & 3) * 8;
    const int br = tid >> 4, bc = (tid & 15) * 8;

    auto a_ptr = [&](int s, int r, int c) -> char* {
        return sm + s * STAGE_B + r * A_ROW_B + c * 2;
    };
    auto b_ptr = [&](int s, int r, int c) -> char* {
        return sm + s * STAGE_B + A_STAGE_B + r * B_ROW_B + c * 2;
    };

    auto load_stage = [&](int s, int kt) {
        const int k0 = kt * GBK;
#pragma unroll
        for (int rr = 0; rr < 2; ++rr)
            cp_async16(a_ptr(s, ar + rr * 64, ac),
                       A + (size_t)(bm + ar + rr * 64) * K + k0 + ac);
#pragma unroll
        for (int rr = 0; rr < 2; ++rr)
            cp_async16(b_ptr(s, br + rr * 16, bc),
                       Bw + (size_t)(k0 + br + rr * 16) * N + bn + bc);
        CP_COMMIT();
    };

    load_stage(0, 0);
    load_stage(1, 1);
    load_stage(2, 2);                      // KT=32 or 64 >= 4 always

    const int arow0 = wm * 64 + (lane & 15);
    const int hi8   = ((lane >> 4) & 1) << 3;
    const int brow0 = lane & 15;

    for (int kt = 0; kt < KT; ++kt) {
        const int s = kt % NSTG;
        int rem = KT - 1 - kt; if (rem > NSTG - 2) rem = NSTG - 2;
        cp_wait_dyn(rem);                  // stage s complete
        __syncthreads();                   // all warps done with stage (kt+3)%4
        if (kt + 3 < KT) load_stage((kt + 3) % NSTG, kt + 3);

#pragma unroll
        for (int ks = 0; ks < GBK; ks += 16) {
            uint32_t afr[4][4], bfr[2][4];
#pragma unroll
            for (int i = 0; i < 4; ++i)
                ldsm_x4(afr[i], a_ptr(s, arow0 + i * 16, ks + hi8));
            const int brow = ks + brow0;
#pragma unroll
            for (int j = 0; j < 2; ++j)
                ldsm_x4_t(bfr[j], b_ptr(s, brow, wn * 32 + j * 16 + hi8));
#pragma unroll
            for (int i = 0; i < 4; ++i)
#pragma unroll
                for (int j = 0; j < 2; ++j) {
                    mma16816(acc[i][2 * j + 0], afr[i], bfr[j][0], bfr[j][1]);
                    mma16816(acc[i][2 * j + 1], afr[i], bfr[j][2], bfr[j][3]);
                }
        }
    }

    // ------------------------------ epilogue ------------------------------
#pragma unroll
    for (int i = 0; i < 4; ++i) {
#pragma unroll
        for (int j = 0; j < 4; ++j) {
            const int mrow0 = bm + wm * 64 + i * 16 + (lane >> 2);
            const int ncol  = bn + wn * 32 + j * 8 + (lane & 3) * 2;
#pragma unroll
            for (int h = 0; h < 2; ++h) {
                const int row = mrow0 + h * 8;
                float v0 = acc[i][j][h * 2 + 0] + bias[ncol];
                float v1 = acc[i][j][h * 2 + 1] + bias[ncol + 1];
                if constexpr (MODE == 0 || MODE == 2) {
                    if constexpr (MODE == 0) { v0 = gelu_erf_f(v0);  v1 = gelu_erf_f(v1); }
                    else                     { v0 = gelu_tanh_f(v0); v1 = gelu_tanh_f(v1); }
                    __nv_bfloat162 p;
                    p.x = __float2bfloat16(v0);
                    p.y = __float2bfloat16(v1);
                    *reinterpret_cast<__nv_bfloat162*>(outb + (size_t)row * N + ncol) = p;
                } else {
                    int orow = row;
                    if constexpr (COMPACT) {
                        if (row >= cnt) continue;
                        orow = g_ridx[row];
                    }
                    const int b = orow >> 11;
                    const float g0 = gate_base[b * 3072 + ncol];
                    const float g1 = gate_base[b * 3072 + ncol + 1];
                    float2 r;
                    r.x = res[(size_t)orow * N + ncol]     + g0 * v0;
                    r.y = res[(size_t)orow * N + ncol + 1] + g1 * v1;
                    *reinterpret_cast<float2*>(outf + (size_t)orow * N + ncol) = r;
                }
            }
        }
    }
}

// --------------------------- launch ------------------------------------------
extern "C" void kernel_launch(void* const* d_in, const int* in_sizes, int n_in,
                              void* d_out, int out_size)
{
    const float* x       = (const float*)d_in[0];
    const float* t       = (const float*)d_in[1];
    const int*   mask    = (const int*)  d_in[2];
    const float* ada_w   = (const float*)d_in[3];
    const float* ada_b   = (const float*)d_in[4];
    const float* ssm_w1  = (const float*)d_in[5];
    const float* ssm_b1  = (const float*)d_in[6];
    const float* ssm_w2  = (const float*)d_in[7];
    const float* ssm_b2  = (const float*)d_in[8];
    const float* bwd_w1  = (const float*)d_in[9];
    const float* bwd_b1  = (const float*)d_in[10];
    const float* bwd_w2  = (const float*)d_in[11];
    const float* bwd_b2  = (const float*)d_in[12];
    const float* ffada_w = (const float*)d_in[13];
    const float* ffada_b = (const float*)d_in[14];
    const float* ff_w1   = (const float*)d_in[15];
    const float* ff_b1   = (const float*)d_in[16];
    const float* ff_w2   = (const float*)d_in[17];
    const float* ff_b2   = (const float*)d_in[18];

    void *p_norm, *p_hcat, *p_x2, *p_w1, *p_w2, *p_fw1, *p_fw2, *p_emb, *p_b1, *p_b2;
    cudaGetSymbolAddress(&p_norm, g_norm);
    cudaGetSymbolAddress(&p_hcat, g_hcat);
    cudaGetSymbolAddress(&p_x2,   g_x2);
    cudaGetSymbolAddress(&p_w1,   g_wcat1);
    cudaGetSymbolAddress(&p_w2,   g_wcat2);
    cudaGetSymbolAddress(&p_fw1,  g_ffw1);
    cudaGetSymbolAddress(&p_fw2,  g_ffw2);
    cudaGetSymbolAddress(&p_emb,  g_emb);
    cudaGetSymbolAddress(&p_b1,   g_bcat1);
    cudaGetSymbolAddress(&p_b2,   g_bcat2);

    __nv_bfloat16* norm = (__nv_bfloat16*)p_norm;
    __nv_bfloat16* hcat = (__nv_bfloat16*)p_hcat;
    float*         x2   = (float*)p_x2;
    float*         emb  = (float*)p_emb;

    cudaFuncSetAttribute(gemm_bf16<0,1>, cudaFuncAttributeMaxDynamicSharedMemorySize, SMEM_DYN);
    cudaFuncSetAttribute(gemm_bf16<1,1>, cudaFuncAttributeMaxDynamicSharedMemorySize, SMEM_DYN);
    cudaFuncSetAttribute(gemm_bf16<2,0>, cudaFuncAttributeMaxDynamicSharedMemorySize, SMEM_DYN);
    cudaFuncSetAttribute(gemm_bf16<3,0>, cudaFuncAttributeMaxDynamicSharedMemorySize, SMEM_DYN);

    // 1. adaLN embeddings (split-K two-phase)
    emb_part_kernel<<<dim3(24, 8), 256>>>(t, ada_w, ffada_w);
    emb_reduce_kernel<<<192, 256>>>(ada_b, ffada_b);

    // 2. pack/convert weights to bf16
    {
        long total = 4L * 1024 * 2048 + 3072;
        int blocks = (int)((total + 255) / 256);
        pack_kernel<<<blocks, 256>>>(ssm_w1, bwd_w1, ssm_w2, bwd_w2, ff_w1, ff_w2,
                                     ssm_b1, bwd_b1, ssm_b2, bwd_b2);
    }

    // 3. mask scan -> compact positions
    scan_kernel<<<1, 1024>>>(mask);

    // 4. LN1 + modulation, compacted to unmasked rows
    ln_mod_kernel<0><<<MTOK / 8, 256>>>(x, nullptr, emb, mask, norm, nullptr);
    zero_pad_kernel<<<128, 256>>>();

    // 5. hcat_c = gelu_erf(norm_c @ Wcat1 + bcat1)    [count,2048] compact
    gemm_bf16<0,1><<<dim3(DFF / GBN, MTOK / GBM), 256, SMEM_DYN>>>(
        norm, (const __nv_bfloat16*)p_w1, (const float*)p_b1, DFF, DDIM,
        nullptr, nullptr, nullptr, hcat);

    // 6. x2[ridx] = x[ridx] + gate_msa * (hcat_c @ Wcat2 + bcat2)  scatter
    gemm_bf16<1,1><<<dim3(DDIM / GBN, MTOK / GBM), 256, SMEM_DYN>>>(
        hcat, (const __nv_bfloat16*)p_w2, (const float*)p_b2, DDIM, DFF,
        x, emb + 2048, x2, nullptr);

    // 7. LN2 + modulation (all rows); masked rows read x and store x2 = x
    ln_mod_kernel<1><<<MTOK / 8, 256>>>(x2, x, emb + 8 * 3072, mask, norm, x2);

    // 8. h = gelu_tanh(norm @ ff_w1 + ff_b1)          [M,2048]
    gemm_bf16<2,0><<<dim3(DFF / GBN, MTOK / GBM), 256, SMEM_DYN>>>(
        norm, (const __nv_bfloat16*)p_fw1, ff_b1, DFF, DDIM,
        nullptr, nullptr, nullptr, hcat);

    // 9. out = x2 + gate_mlp * (h @ ff_w2 + ff_b2)    [M,1024] fp32 -> d_out
    gemm_bf16<3,0><<<dim3(DDIM / GBN, MTOK / GBM), 256, SMEM_DYN>>>(
        hcat, (const __nv_bfloat16*)p_fw2, ff_b2, DDIM, DFF,
        x2, emb + 8 * 3072 + 2048, (float*)d_out, nullptr);
}